// round 5
// baseline (speedup 1.0000x reference)
#include <cuda_runtime.h>
#include <cuda_fp16.h>
#include <cstdint>

#define N_NODES   100000
#define DIM       512
#define TILE_M    64
#define KCH       64                 // K elems per chunk (64 halfs = 128B data row)
#define N_CHUNKS  8
#define THREADS   512
#define NUM_TILES ((N_NODES + TILE_M - 1) / TILE_M)   // 1563

// SMEM rows: 128B fp16 data padded to 160B (40 words) -> conflict-free LDS.64
#define ROW_BYTES   160
#define A_BYTES     (TILE_M * ROW_BYTES)      // 10240
#define B_BYTES     (512 * ROW_BYTES)         // 81920
#define STAGE_BYTES (A_BYTES + B_BYTES)       // 92160

#define SM_BIAS   0
#define SM_GAMMA  2048
#define SM_BETA   4096
#define SM_RSUM   6144                        // [64][8] f32
#define SM_RSQ    8192                        // [64][8] f32
#define SM_MEAN   10240
#define SM_RSTD   10496
#define SM_STAGE  11264                       // 1024-aligned
#define SMEM_TOTAL (SM_STAGE + 2 * STAGE_BYTES)   // 195584

#define OUT_STRIDE_W 520                      // epilogue staging stride (words)

__device__ __half g_Wh[512 * 512];            // pre-converted W (512KB, L2-resident)

static __device__ __forceinline__ uint32_t smem_u32(const void* p) {
    uint32_t a;
    asm("{ .reg .u64 t; cvta.to.shared.u64 t, %1; cvt.u32.u64 %0, t; }" : "=r"(a) : "l"(p));
    return a;
}

static __device__ __forceinline__ uint2 lds64(uint32_t a) {
    uint2 v;
    asm volatile("ld.shared.v2.b32 {%0, %1}, [%2];" : "=r"(v.x), "=r"(v.y) : "r"(a));
    return v;
}

// m16n8k16 fp16 MMA; physical k cols 4q..4q+3 carry logical {2q,2q+1,2q+8,2q+9}
// (consistent A/B relabeling -> dot product invariant).
static __device__ __forceinline__ void mma_f16(float* d, uint2 lo, uint2 hi, uint2 b) {
    asm volatile(
        "mma.sync.aligned.m16n8k16.row.col.f32.f16.f16.f32 "
        "{%0,%1,%2,%3}, {%4,%5,%6,%7}, {%8,%9}, {%0,%1,%2,%3};"
        : "+f"(d[0]), "+f"(d[1]), "+f"(d[2]), "+f"(d[3])
        : "r"(lo.x), "r"(hi.x), "r"(lo.y), "r"(hi.y), "r"(b.x), "r"(b.y));
}

static __device__ __forceinline__ void cp16(uint32_t dst, const void* src) {
    asm volatile("cp.async.cg.shared.global [%0], [%1], 16;" :: "r"(dst), "l"(src));
}

// B chunk: 512 rows x 128B fp16 from g_Wh into stage (160B padded rows)
static __device__ __forceinline__ void load_B(int kc, uint32_t b_base, int tid) {
#pragma unroll
    for (int it = 0; it < 8; it++) {
        int id  = it * THREADS + tid;
        int row = id >> 3, j = id & 7;
        cp16(b_base + (uint32_t)(row * ROW_BYTES + j * 16),
             g_Wh + (size_t)row * DIM + kc * KCH + j * 8);
    }
}

// A chunk LDG: thread -> row tid>>3, 8 floats at float col (tid&7)*8
static __device__ __forceinline__ void ldg_A(const float* __restrict__ x,
                                             int m0, int kc, int tid, float4* r) {
    int row = tid >> 3;
    int gr  = m0 + row;
    if (gr > N_NODES - 1) gr = N_NODES - 1;   // clamped rows never stored
    const float* p = x + (size_t)gr * DIM + kc * KCH + (tid & 7) * 8;
    r[0] = *(const float4*)(p);
    r[1] = *(const float4*)(p + 4);
}

// convert + store A chunk regs (8 floats -> 8 halfs = 16B) into stage A region
static __device__ __forceinline__ void sts_A(uint32_t a_base, int tid, const float4* r) {
    uint32_t a = a_base + (uint32_t)((tid >> 3) * ROW_BYTES + (tid & 7) * 16);
    __half2 x0 = __floats2half2_rn(r[0].x, r[0].y);
    __half2 x1 = __floats2half2_rn(r[0].z, r[0].w);
    __half2 x2 = __floats2half2_rn(r[1].x, r[1].y);
    __half2 x3 = __floats2half2_rn(r[1].z, r[1].w);
    asm volatile("st.shared.v4.b32 [%0], {%1,%2,%3,%4};" :: "r"(a),
                 "r"(*(uint32_t*)&x0), "r"(*(uint32_t*)&x1),
                 "r"(*(uint32_t*)&x2), "r"(*(uint32_t*)&x3) : "memory");
}

__global__ void wconv_kernel(const float* __restrict__ W) {
    int i = (blockIdx.x * blockDim.x + threadIdx.x) * 4;
    float4 v = *(const float4*)(W + i);
    __half2 h0 = __floats2half2_rn(v.x, v.y);
    __half2 h1 = __floats2half2_rn(v.z, v.w);
    *(__half2*)(g_Wh + i)     = h0;
    *(__half2*)(g_Wh + i + 2) = h1;
}

__global__ void __launch_bounds__(THREADS, 1)
fused_gemm_ln_lrelu(const float* __restrict__ x,
                    const float* __restrict__ bias, const float* __restrict__ gamma,
                    const float* __restrict__ beta, float* __restrict__ out) {
    extern __shared__ __align__(1024) char smem[];
    const uint32_t sb = smem_u32(smem);
    const int tid  = threadIdx.x;
    const int lane = tid & 31;
    const int wid  = tid >> 5;          // 0..15
    const int q    = lane & 3;
    const int g    = lane >> 2;
    const int mh   = wid >> 3;          // M half: rows [32*mh, 32*mh+32)
    const int nw   = wid & 7;           // N slice: cols [64*nw, 64*nw+64)
    const int m0   = blockIdx.x * TILE_M;

    {
        int c = tid;
        if (c < 512) {
            ((float*)(smem + SM_BIAS))[c]  = bias[c];
            ((float*)(smem + SM_GAMMA))[c] = gamma[c];
            ((float*)(smem + SM_BETA))[c]  = beta[c];
        }
    }

    float acc[2][8][4];
#pragma unroll
    for (int mt = 0; mt < 2; mt++)
#pragma unroll
        for (int nt = 0; nt < 8; nt++)
#pragma unroll
            for (int u = 0; u < 4; u++) acc[mt][nt][u] = 0.f;

    const uint32_t st0 = sb + SM_STAGE;
    const uint32_t st1 = st0 + STAGE_BYTES;

    // prologue: A0 via LDG->cvt->STS ; B0, B1 via cp.async
    float4 r[2];
    ldg_A(x, m0, 0, tid, r);
    load_B(0, st0 + A_BYTES, tid);
    asm volatile("cp.async.commit_group;" ::: "memory");
    sts_A(st0, tid, r);
    ldg_A(x, m0, 1, tid, r);
    load_B(1, st1 + A_BYTES, tid);
    asm volatile("cp.async.commit_group;" ::: "memory");

    const uint32_t wb = (uint32_t)nw * 64;      // warp n-base
    const uint32_t mbase = (uint32_t)(mh * 32); // warp m-base

#pragma unroll 1
    for (int i = 0; i < N_CHUNKS; i++) {
        const uint32_t SA  = (i & 1) ? st1 : st0;
        const uint32_t SAo = (i & 1) ? st0 : st1;   // other stage
        if (i < N_CHUNKS - 1) asm volatile("cp.async.wait_group 1;" ::: "memory");
        else                  asm volatile("cp.async.wait_group 0;" ::: "memory");
        __syncthreads();   // B(i)+A(i) visible; other stage fully consumed

        if (i + 1 < N_CHUNKS) {
            sts_A(SAo, tid, r);                 // A(i+1) into other stage
            if (i + 2 < N_CHUNKS) ldg_A(x, m0, i + 2, tid, r);
        }

        const uint32_t SBS = SA + A_BYTES;
#pragma unroll
        for (int s = 0; s < 4; s++) {
            const uint32_t kb = (uint32_t)(s * 32 + q * 8);
            uint2 alo[2], ahi[2];
#pragma unroll
            for (int mt = 0; mt < 2; mt++) {
                uint32_t ar = SA + (mbase + 16 * mt + (uint32_t)g) * ROW_BYTES + kb;
                alo[mt] = lds64(ar);
                ahi[mt] = lds64(ar + 8 * ROW_BYTES);
            }
            uint2 bf[8];
#pragma unroll
            for (int nt = 0; nt < 8; nt++)
                bf[nt] = lds64(SBS + (wb + 8 * nt + (uint32_t)g) * ROW_BYTES + kb);
#pragma unroll
            for (int mt = 0; mt < 2; mt++)
#pragma unroll
                for (int nt = 0; nt < 8; nt++)
                    mma_f16(acc[mt][nt], alo[mt], ahi[mt], bf[nt]);
        }
        __syncthreads();   // all warps done reading stage SA

        if (i + 2 < N_CHUNKS) {
            load_B(i + 2, SA + A_BYTES, tid);   // reuse just-freed stage
            asm volatile("cp.async.commit_group;" ::: "memory");
        }
    }

    // ---------------- epilogue ----------------
    const float* bs = (const float*)(smem + SM_BIAS);
    const float* gs = (const float*)(smem + SM_GAMMA);
    const float* es = (const float*)(smem + SM_BETA);
    float* rsum  = (float*)(smem + SM_RSUM);
    float* rsq   = (float*)(smem + SM_RSQ);
    float* smean = (float*)(smem + SM_MEAN);
    float* srstd = (float*)(smem + SM_RSTD);

#pragma unroll
    for (int nt = 0; nt < 8; nt++) {
        int c0 = (int)wb + 8 * nt + 2 * q;
        float b0 = bs[c0], b1 = bs[c0 + 1];
#pragma unroll
        for (int mt = 0; mt < 2; mt++) {
            acc[mt][nt][0] += b0; acc[mt][nt][1] += b1;
            acc[mt][nt][2] += b0; acc[mt][nt][3] += b1;
        }
    }

    // per-row partial sums: rows mbase+16mt+g (sA) and mbase+16mt+8+g (sB)
    float sA[2], qA[2], sB[2], qB[2];
#pragma unroll
    for (int mt = 0; mt < 2; mt++) {
        float s0 = 0.f, q0 = 0.f, s1 = 0.f, q1 = 0.f;
#pragma unroll
        for (int nt = 0; nt < 8; nt++) {
            float v0 = acc[mt][nt][0], v1 = acc[mt][nt][1];
            float v2 = acc[mt][nt][2], v3 = acc[mt][nt][3];
            s0 += v0 + v1;  q0 += v0 * v0 + v1 * v1;
            s1 += v2 + v3;  q1 += v2 * v2 + v3 * v3;
        }
        sA[mt] = s0; qA[mt] = q0; sB[mt] = s1; qB[mt] = q1;
    }
#pragma unroll
    for (int off = 1; off <= 2; off <<= 1) {
#pragma unroll
        for (int mt = 0; mt < 2; mt++) {
            sA[mt] += __shfl_xor_sync(0xffffffffu, sA[mt], off);
            qA[mt] += __shfl_xor_sync(0xffffffffu, qA[mt], off);
            sB[mt] += __shfl_xor_sync(0xffffffffu, sB[mt], off);
            qB[mt] += __shfl_xor_sync(0xffffffffu, qB[mt], off);
        }
    }
    if (q == 0) {
#pragma unroll
        for (int mt = 0; mt < 2; mt++) {
            int rA = (int)mbase + 16 * mt + g;
            rsum[rA * 8 + nw]       = sA[mt];
            rsq [rA * 8 + nw]       = qA[mt];
            rsum[(rA + 8) * 8 + nw] = sB[mt];
            rsq [(rA + 8) * 8 + nw] = qB[mt];
        }
    }
    __syncthreads();

    if (tid < 64) {
        float s = 0.f, ss = 0.f;
#pragma unroll
        for (int w = 0; w < 8; w++) { s += rsum[tid * 8 + w]; ss += rsq[tid * 8 + w]; }
        float mean = s * (1.0f / 512.0f);
        float var  = ss * (1.0f / 512.0f) - mean * mean;
        smean[tid] = mean;
        srstd[tid] = rsqrtf(var + 1e-5f);
    }
    __syncthreads();

    const uint32_t OS = sb + SM_STAGE;
#pragma unroll
    for (int mt = 0; mt < 2; mt++) {
        int rA = (int)mbase + 16 * mt + g, rB = rA + 8;
        float mA = smean[rA], rsdA = srstd[rA];
        float mB = smean[rB], rsdB = srstd[rB];
#pragma unroll
        for (int nt = 0; nt < 8; nt++) {
            int c0 = (int)wb + 8 * nt + 2 * q;
            float g0 = gs[c0], g1 = gs[c0 + 1];
            float e0 = es[c0], e1 = es[c0 + 1];
            float t0 = (acc[mt][nt][0] - mA) * rsdA * g0 + e0;
            float t1 = (acc[mt][nt][1] - mA) * rsdA * g1 + e1;
            float t2 = (acc[mt][nt][2] - mB) * rsdB * g0 + e0;
            float t3 = (acc[mt][nt][3] - mB) * rsdB * g1 + e1;
            t0 = fmaxf(t0, 0.2f * t0);
            t1 = fmaxf(t1, 0.2f * t1);
            t2 = fmaxf(t2, 0.2f * t2);
            t3 = fmaxf(t3, 0.2f * t3);
            uint32_t a0 = OS + (uint32_t)(rA * OUT_STRIDE_W + c0) * 4;
            uint32_t a1 = OS + (uint32_t)(rB * OUT_STRIDE_W + c0) * 4;
            asm volatile("st.shared.v2.f32 [%0], {%1, %2};" :: "r"(a0), "f"(t0), "f"(t1) : "memory");
            asm volatile("st.shared.v2.f32 [%0], {%1, %2};" :: "r"(a1), "f"(t2), "f"(t3) : "memory");
        }
    }
    __syncthreads();

    // coalesced writeback: 64 rows x 512 floats = 8192 float4s, 512 threads -> 16 iters
#pragma unroll
    for (int it = 0; it < 16; it++) {
        int id  = it * THREADS + tid;
        int row = id >> 7;
        int j   = id & 127;
        int gr  = m0 + row;
        if (gr < N_NODES) {
            uint32_t a = OS + (uint32_t)(row * OUT_STRIDE_W + j * 4) * 4;
            uint32_t v0, v1, v2, v3;
            asm volatile("ld.shared.v4.b32 {%0, %1, %2, %3}, [%4];"
                         : "=r"(v0), "=r"(v1), "=r"(v2), "=r"(v3) : "r"(a));
            float4 o;
            o.x = __uint_as_float(v0); o.y = __uint_as_float(v1);
            o.z = __uint_as_float(v2); o.w = __uint_as_float(v3);
            *(float4*)(out + (size_t)gr * DIM + j * 4) = o;
        }
    }
}

extern "C" void kernel_launch(void* const* d_in, const int* in_sizes, int n_in,
                              void* d_out, int out_size) {
    const float* x     = (const float*)d_in[0];
    // d_in[1] edge_attr, d_in[2] edge_index, d_in[3] batch: dead inputs
    const float* W     = (const float*)d_in[4];
    const float* bias  = (const float*)d_in[5];
    const float* gamma = (const float*)d_in[6];
    const float* beta  = (const float*)d_in[7];
    float* out = (float*)d_out;

    wconv_kernel<<<256, 256>>>(W);

    cudaFuncSetAttribute(fused_gemm_ln_lrelu,
                         cudaFuncAttributeMaxDynamicSharedMemorySize, SMEM_TOTAL);
    fused_gemm_ln_lrelu<<<NUM_TILES, THREADS, SMEM_TOTAL>>>(x, bias, gamma, beta, out);
}

// round 6
// speedup vs baseline: 1.1652x; 1.1652x over previous
#include <cuda_runtime.h>
#include <cuda_fp16.h>
#include <cstdint>

#define N_NODES   100000
#define DIM       512
#define TILE_M    64
#define KCH       64                 // K halfs per chunk (128B per row)
#define N_CHUNKS  8
#define THREADS   512
#define NUM_TILES ((N_NODES + TILE_M - 1) / TILE_M)   // 1563

// XOR-swizzled rows: 128B, granule g at (g ^ (row&7))*16
#define A_STAGE   8192               // 64 rows x 128B
#define B_STAGE   65536              // 512 rows x 128B

#define SM_BIAS   0
#define SM_GAMMA  2048
#define SM_BETA   4096
#define SM_RSUM   6144               // [64][8] f32
#define SM_RSQ    8192               // [64][8] f32
#define SM_MEAN   10240
#define SM_RSTD   10496
#define SM_A      11264              // 2 stages
#define SM_B      27648              // 3 stages
#define SMEM_TOTAL (SM_B + 3 * B_STAGE)   // 224256

#define OUT_STRIDE_W 520             // epilogue staging stride (words)

__device__ __half g_Wh[512 * 512];   // pre-converted W (512KB, L2-resident)

static __device__ __forceinline__ uint32_t smem_u32(const void* p) {
    uint32_t a;
    asm("{ .reg .u64 t; cvta.to.shared.u64 t, %1; cvt.u32.u64 %0, t; }" : "=r"(a) : "l"(p));
    return a;
}

#define LDSM4(r, a) \
    asm volatile("ldmatrix.sync.aligned.m8n8.x4.shared.b16 {%0,%1,%2,%3}, [%4];" \
        : "=r"((r)[0]), "=r"((r)[1]), "=r"((r)[2]), "=r"((r)[3]) : "r"(a))

static __device__ __forceinline__ void mma_f16(float* d, const uint32_t* a,
                                               uint32_t b0, uint32_t b1) {
    asm volatile(
        "mma.sync.aligned.m16n8k16.row.col.f32.f16.f16.f32 "
        "{%0,%1,%2,%3}, {%4,%5,%6,%7}, {%8,%9}, {%0,%1,%2,%3};"
        : "+f"(d[0]), "+f"(d[1]), "+f"(d[2]), "+f"(d[3])
        : "r"(a[0]), "r"(a[1]), "r"(a[2]), "r"(a[3]), "r"(b0), "r"(b1));
}

static __device__ __forceinline__ void cp16(uint32_t dst, const void* src) {
    asm volatile("cp.async.cg.shared.global [%0], [%1], 16;" :: "r"(dst), "l"(src));
}

// B chunk: 512 rows x 128B fp16 from g_Wh, XOR-swizzled
static __device__ __forceinline__ void load_B(int kc, uint32_t b_base, int tid) {
#pragma unroll
    for (int it = 0; it < 8; it++) {
        int id  = it * THREADS + tid;
        int row = id >> 3, j = id & 7;
        cp16(b_base + (uint32_t)(row * 128 + ((j ^ (row & 7)) << 4)),
             g_Wh + (size_t)row * DIM + kc * KCH + j * 8);
    }
}

// A chunk LDG: thread -> row tid>>3, 8 f32 at col (tid&7)*8
static __device__ __forceinline__ void ldg_A(const float* __restrict__ x,
                                             int m0, int kc, int tid, float4* r) {
    int row = tid >> 3;
    int gr  = m0 + row;
    if (gr > N_NODES - 1) gr = N_NODES - 1;   // clamped rows never stored
    const float* p = x + (size_t)gr * DIM + kc * KCH + (tid & 7) * 8;
    r[0] = *(const float4*)(p);
    r[1] = *(const float4*)(p + 4);
}

// convert + store A chunk (8 f32 -> 8 halfs = 1 granule), XOR-swizzled
static __device__ __forceinline__ void sts_A(uint32_t a_base, int tid, const float4* r) {
    int row = tid >> 3, j = tid & 7;
    uint32_t a = a_base + (uint32_t)(row * 128 + ((j ^ (row & 7)) << 4));
    __half2 x0 = __floats2half2_rn(r[0].x, r[0].y);
    __half2 x1 = __floats2half2_rn(r[0].z, r[0].w);
    __half2 x2 = __floats2half2_rn(r[1].x, r[1].y);
    __half2 x3 = __floats2half2_rn(r[1].z, r[1].w);
    asm volatile("st.shared.v4.b32 [%0], {%1,%2,%3,%4};" :: "r"(a),
                 "r"(*(uint32_t*)&x0), "r"(*(uint32_t*)&x1),
                 "r"(*(uint32_t*)&x2), "r"(*(uint32_t*)&x3) : "memory");
}

__global__ void wconv_kernel(const float* __restrict__ W) {
    int i = (blockIdx.x * blockDim.x + threadIdx.x) * 4;
    float4 v = *(const float4*)(W + i);
    __half2 h0 = __floats2half2_rn(v.x, v.y);
    __half2 h1 = __floats2half2_rn(v.z, v.w);
    *(__half2*)(g_Wh + i)     = h0;
    *(__half2*)(g_Wh + i + 2) = h1;
}

__global__ void __launch_bounds__(THREADS, 1)
fused_gemm_ln_lrelu(const float* __restrict__ x,
                    const float* __restrict__ bias, const float* __restrict__ gamma,
                    const float* __restrict__ beta, float* __restrict__ out) {
    extern __shared__ __align__(1024) char smem[];
    const uint32_t sb = smem_u32(smem);
    const int tid  = threadIdx.x;
    const int lane = tid & 31;
    const int wid  = tid >> 5;          // 0..15
    const int q    = lane & 3;
    const int g    = lane >> 2;
    const int mh   = wid >> 3;          // M half: rows [32*mh, +32)
    const int nw   = wid & 7;           // N slice: cols [64*nw, +64)
    const int m0   = blockIdx.x * TILE_M;

    ((float*)(smem + SM_BIAS))[tid]  = bias[tid];
    ((float*)(smem + SM_GAMMA))[tid] = gamma[tid];
    ((float*)(smem + SM_BETA))[tid]  = beta[tid];

    float acc[2][8][4];
#pragma unroll
    for (int mt = 0; mt < 2; mt++)
#pragma unroll
        for (int nt = 0; nt < 8; nt++)
#pragma unroll
            for (int u = 0; u < 4; u++) acc[mt][nt][u] = 0.f;

    // -------- per-lane ldmatrix address components --------
    // A fragment (m16k16, x4): lanes 0-15 -> rows m0..15 @k-low granule,
    // lanes 16-31 -> same rows @k-high granule.
    const int mr0 = mh * 32 + (lane & 15);        // mt=0 row
    const int mr1 = mr0 + 16;                     // mt=1 row
    const int agsel = lane >> 4;                  // 0/1 (k-low/high 8)
    const uint32_t aoff0 = (uint32_t)(mr0 * 128);
    const uint32_t aoff1 = (uint32_t)(mr1 * 128);
    const int m7_0 = mr0 & 7, m7_1 = mr1 & 7;
    // B fragments (pair of n8k16 per LDSM.x4): lanes 0-7 n+0..7 klow,
    // 8-15 same rows khigh, 16-23 n+8..15 klow, 24-31 khigh.
    const int wb = nw * 64;
    int nr[4], n7[4];
    uint32_t boff[4];
    const int bgsel = (lane >> 3) & 1;
#pragma unroll
    for (int p = 0; p < 4; p++) {
        nr[p] = wb + p * 16 + (lane & 7) + ((lane >> 4) << 3);
        n7[p] = nr[p] & 7;
        boff[p] = (uint32_t)(nr[p] * 128);
    }

    const uint32_t ab = sb + SM_A;
    const uint32_t bb = sb + SM_B;

    // -------- prologue --------
    float4 r[2];
    ldg_A(x, m0, 0, tid, r);
    load_B(0, bb, tid);
    asm volatile("cp.async.commit_group;" ::: "memory");
    sts_A(ab, tid, r);
    ldg_A(x, m0, 1, tid, r);
    load_B(1, bb + B_STAGE, tid);
    asm volatile("cp.async.commit_group;" ::: "memory");

    int bidx = 0;   // B stage of current chunk

#pragma unroll 1
    for (int i = 0; i < N_CHUNKS; i++) {
        if (i < N_CHUNKS - 1) asm volatile("cp.async.wait_group 1;" ::: "memory");
        else                  asm volatile("cp.async.wait_group 0;" ::: "memory");
        __syncthreads();   // B(i),A(i) visible; stages for (i+2)/(i+1) drained

        // issue next loads into drained stages
        if (i + 2 < N_CHUNKS) {
            int b2 = bidx + 2; if (b2 >= 3) b2 -= 3;
            load_B(i + 2, bb + (uint32_t)b2 * B_STAGE, tid);
            asm volatile("cp.async.commit_group;" ::: "memory");
        }
        if (i + 1 < N_CHUNKS) {
            sts_A(ab + (uint32_t)((i + 1) & 1) * A_STAGE, tid, r);
            if (i + 2 < N_CHUNKS) ldg_A(x, m0, i + 2, tid, r);
        }

        const uint32_t SA  = ab + (uint32_t)(i & 1) * A_STAGE;
        const uint32_t SBs = bb + (uint32_t)bidx * B_STAGE;

        // -------- fragment-pipelined compute: 4 ks steps of k16 --------
        uint32_t af[2][2][4], bf[2][4][4];
#pragma unroll
        {
            const int c2 = 0;
            LDSM4(af[0][0], SA + aoff0 + (uint32_t)(((c2 + agsel) ^ m7_0) << 4));
            LDSM4(af[0][1], SA + aoff1 + (uint32_t)(((c2 + agsel) ^ m7_1) << 4));
#pragma unroll
            for (int p = 0; p < 4; p++)
                LDSM4(bf[0][p], SBs + boff[p] + (uint32_t)(((c2 + bgsel) ^ n7[p]) << 4));
        }
#pragma unroll
        for (int ks = 0; ks < 4; ks++) {
            const int cur = ks & 1, nxt = cur ^ 1;
            if (ks < 3) {
                const int c2 = 2 * (ks + 1);
                LDSM4(af[nxt][0], SA + aoff0 + (uint32_t)(((c2 + agsel) ^ m7_0) << 4));
                LDSM4(af[nxt][1], SA + aoff1 + (uint32_t)(((c2 + agsel) ^ m7_1) << 4));
#pragma unroll
                for (int p = 0; p < 4; p++)
                    LDSM4(bf[nxt][p], SBs + boff[p] + (uint32_t)(((c2 + bgsel) ^ n7[p]) << 4));
            }
#pragma unroll
            for (int mt = 0; mt < 2; mt++)
#pragma unroll
                for (int p = 0; p < 4; p++) {
                    mma_f16(acc[mt][2 * p],     af[cur][mt], bf[cur][p][0], bf[cur][p][1]);
                    mma_f16(acc[mt][2 * p + 1], af[cur][mt], bf[cur][p][2], bf[cur][p][3]);
                }
        }

        if (++bidx == 3) bidx = 0;
    }

    // ---------------- epilogue ----------------
    const float* bs = (const float*)(smem + SM_BIAS);
    const float* gs = (const float*)(smem + SM_GAMMA);
    const float* es = (const float*)(smem + SM_BETA);
    float* rsum  = (float*)(smem + SM_RSUM);
    float* rsq   = (float*)(smem + SM_RSQ);
    float* smean = (float*)(smem + SM_MEAN);
    float* srstd = (float*)(smem + SM_RSTD);
    const uint32_t mbase = (uint32_t)(mh * 32);

#pragma unroll
    for (int nt = 0; nt < 8; nt++) {
        int c0 = wb + 8 * nt + 2 * q;
        float b0 = bs[c0], b1 = bs[c0 + 1];
#pragma unroll
        for (int mt = 0; mt < 2; mt++) {
            acc[mt][nt][0] += b0; acc[mt][nt][1] += b1;
            acc[mt][nt][2] += b0; acc[mt][nt][3] += b1;
        }
    }

    float sA[2], qA[2], sB[2], qB[2];
#pragma unroll
    for (int mt = 0; mt < 2; mt++) {
        float s0 = 0.f, q0 = 0.f, s1 = 0.f, q1 = 0.f;
#pragma unroll
        for (int nt = 0; nt < 8; nt++) {
            float v0 = acc[mt][nt][0], v1 = acc[mt][nt][1];
            float v2 = acc[mt][nt][2], v3 = acc[mt][nt][3];
            s0 += v0 + v1;  q0 += v0 * v0 + v1 * v1;
            s1 += v2 + v3;  q1 += v2 * v2 + v3 * v3;
        }
        sA[mt] = s0; qA[mt] = q0; sB[mt] = s1; qB[mt] = q1;
    }
#pragma unroll
    for (int off = 1; off <= 2; off <<= 1) {
#pragma unroll
        for (int mt = 0; mt < 2; mt++) {
            sA[mt] += __shfl_xor_sync(0xffffffffu, sA[mt], off);
            qA[mt] += __shfl_xor_sync(0xffffffffu, qA[mt], off);
            sB[mt] += __shfl_xor_sync(0xffffffffu, sB[mt], off);
            qB[mt] += __shfl_xor_sync(0xffffffffu, qB[mt], off);
        }
    }
    if (q == 0) {
#pragma unroll
        for (int mt = 0; mt < 2; mt++) {
            int rA = (int)mbase + 16 * mt + g;
            rsum[rA * 8 + nw]       = sA[mt];
            rsq [rA * 8 + nw]       = qA[mt];
            rsum[(rA + 8) * 8 + nw] = sB[mt];
            rsq [(rA + 8) * 8 + nw] = qB[mt];
        }
    }
    __syncthreads();

    if (tid < 64) {
        float s = 0.f, ss = 0.f;
#pragma unroll
        for (int w = 0; w < 8; w++) { s += rsum[tid * 8 + w]; ss += rsq[tid * 8 + w]; }
        float mean = s * (1.0f / 512.0f);
        float var  = ss * (1.0f / 512.0f) - mean * mean;
        smean[tid] = mean;
        srstd[tid] = rsqrtf(var + 1e-5f);
    }
    __syncthreads();

    const uint32_t OS = sb + SM_B;   // staging reuses B region (guarded by 2 syncs above)
#pragma unroll
    for (int mt = 0; mt < 2; mt++) {
        int rA = (int)mbase + 16 * mt + g, rB = rA + 8;
        float mA = smean[rA], rsdA = srstd[rA];
        float mB = smean[rB], rsdB = srstd[rB];
#pragma unroll
        for (int nt = 0; nt < 8; nt++) {
            int c0 = wb + 8 * nt + 2 * q;
            float g0 = gs[c0], g1 = gs[c0 + 1];
            float e0 = es[c0], e1 = es[c0 + 1];
            float t0 = (acc[mt][nt][0] - mA) * rsdA * g0 + e0;
            float t1 = (acc[mt][nt][1] - mA) * rsdA * g1 + e1;
            float t2 = (acc[mt][nt][2] - mB) * rsdB * g0 + e0;
            float t3 = (acc[mt][nt][3] - mB) * rsdB * g1 + e1;
            t0 = fmaxf(t0, 0.2f * t0);
            t1 = fmaxf(t1, 0.2f * t1);
            t2 = fmaxf(t2, 0.2f * t2);
            t3 = fmaxf(t3, 0.2f * t3);
            uint32_t a0 = OS + (uint32_t)(rA * OUT_STRIDE_W + c0) * 4;
            uint32_t a1 = OS + (uint32_t)(rB * OUT_STRIDE_W + c0) * 4;
            asm volatile("st.shared.v2.f32 [%0], {%1, %2};" :: "r"(a0), "f"(t0), "f"(t1) : "memory");
            asm volatile("st.shared.v2.f32 [%0], {%1, %2};" :: "r"(a1), "f"(t2), "f"(t3) : "memory");
        }
    }
    __syncthreads();

    // coalesced writeback: 64 rows x 512 f32 = 8192 float4s
#pragma unroll
    for (int it = 0; it < 16; it++) {
        int id  = it * THREADS + tid;
        int row = id >> 7;
        int j   = id & 127;
        int gr  = m0 + row;
        if (gr < N_NODES) {
            uint32_t a = OS + (uint32_t)(row * OUT_STRIDE_W + j * 4) * 4;
            uint32_t v0, v1, v2, v3;
            asm volatile("ld.shared.v4.b32 {%0, %1, %2, %3}, [%4];"
                         : "=r"(v0), "=r"(v1), "=r"(v2), "=r"(v3) : "r"(a));
            float4 o;
            o.x = __uint_as_float(v0); o.y = __uint_as_float(v1);
            o.z = __uint_as_float(v2); o.w = __uint_as_float(v3);
            *(float4*)(out + (size_t)gr * DIM + j * 4) = o;
        }
    }
}

extern "C" void kernel_launch(void* const* d_in, const int* in_sizes, int n_in,
                              void* d_out, int out_size) {
    const float* x     = (const float*)d_in[0];
    // d_in[1] edge_attr, d_in[2] edge_index, d_in[3] batch: dead inputs
    const float* W     = (const float*)d_in[4];
    const float* bias  = (const float*)d_in[5];
    const float* gamma = (const float*)d_in[6];
    const float* beta  = (const float*)d_in[7];
    float* out = (float*)d_out;

    wconv_kernel<<<256, 256>>>(W);

    cudaFuncSetAttribute(fused_gemm_ln_lrelu,
                         cudaFuncAttributeMaxDynamicSharedMemorySize, SMEM_TOTAL);
    fused_gemm_ln_lrelu<<<NUM_TILES, THREADS, SMEM_TOTAL>>>(x, bias, gamma, beta, out);
}

// round 7
// speedup vs baseline: 1.2206x; 1.0476x over previous
#include <cuda_runtime.h>
#include <cuda_fp16.h>
#include <cstdint>

#define N_NODES   100000
#define DIM       512
#define TILE_M    64
#define KCH       64                 // K halfs per chunk (128B per row)
#define N_CHUNKS  8
#define THREADS   512
#define NUM_TILES ((N_NODES + TILE_M - 1) / TILE_M)   // 1563

// XOR-swizzled rows: 128B, granule g at (g ^ (row&7))*16
#define A_STAGE   8192               // 64 rows x 128B
#define B_STAGE   65536              // 512 rows x 128B

#define SM_BIAS   0
#define SM_GAMMA  2048
#define SM_BETA   4096
#define SM_RSUM   6144               // [64][8] f32
#define SM_RSQ    8192               // [64][8] f32
#define SM_MEAN   10240
#define SM_RSTD   10496
#define SM_A      11264              // 2 stages
#define SM_B      27648              // 3 stages
#define SMEM_TOTAL (SM_B + 3 * B_STAGE)   // 224256

#define OUT_STRIDE_W 520             // epilogue staging stride (words)

__device__ __half g_Wh[512 * 512];   // pre-converted W (512KB, L2-resident)

static __device__ __forceinline__ uint32_t smem_u32(const void* p) {
    uint32_t a;
    asm("{ .reg .u64 t; cvta.to.shared.u64 t, %1; cvt.u32.u64 %0, t; }" : "=r"(a) : "l"(p));
    return a;
}

#define LDSM4(r, a) \
    asm volatile("ldmatrix.sync.aligned.m8n8.x4.shared.b16 {%0,%1,%2,%3}, [%4];" \
        : "=r"((r)[0]), "=r"((r)[1]), "=r"((r)[2]), "=r"((r)[3]) : "r"(a))

static __device__ __forceinline__ void mma_f16(float* d, const uint32_t* a,
                                               uint32_t b0, uint32_t b1) {
    asm volatile(
        "mma.sync.aligned.m16n8k16.row.col.f32.f16.f16.f32 "
        "{%0,%1,%2,%3}, {%4,%5,%6,%7}, {%8,%9}, {%0,%1,%2,%3};"
        : "+f"(d[0]), "+f"(d[1]), "+f"(d[2]), "+f"(d[3])
        : "r"(a[0]), "r"(a[1]), "r"(a[2]), "r"(a[3]), "r"(b0), "r"(b1));
}

static __device__ __forceinline__ void cp16(uint32_t dst, const void* src) {
    asm volatile("cp.async.cg.shared.global [%0], [%1], 16;" :: "r"(dst), "l"(src));
}

// B chunk: 512 rows x 128B fp16 from g_Wh, XOR-swizzled
static __device__ __forceinline__ void load_B(int kc, uint32_t b_base, int tid) {
#pragma unroll
    for (int it = 0; it < 8; it++) {
        int id  = it * THREADS + tid;
        int row = id >> 3, j = id & 7;
        cp16(b_base + (uint32_t)(row * 128 + ((j ^ (row & 7)) << 4)),
             g_Wh + (size_t)row * DIM + kc * KCH + j * 8);
    }
}

// A chunk LDG: thread -> row tid>>3, 8 f32 at col (tid&7)*8
static __device__ __forceinline__ void ldg_A(const float* __restrict__ x,
                                             int m0, int kc, int tid, float4* r) {
    int row = tid >> 3;
    int gr  = m0 + row;
    if (gr > N_NODES - 1) gr = N_NODES - 1;   // clamped rows never stored
    const float* p = x + (size_t)gr * DIM + kc * KCH + (tid & 7) * 8;
    r[0] = *(const float4*)(p);
    r[1] = *(const float4*)(p + 4);
}

// convert + store A chunk (8 f32 -> 8 halfs = 1 granule), XOR-swizzled
static __device__ __forceinline__ void sts_A(uint32_t a_base, int tid, const float4* r) {
    int row = tid >> 3, j = tid & 7;
    uint32_t a = a_base + (uint32_t)(row * 128 + ((j ^ (row & 7)) << 4));
    __half2 x0 = __floats2half2_rn(r[0].x, r[0].y);
    __half2 x1 = __floats2half2_rn(r[0].z, r[0].w);
    __half2 x2 = __floats2half2_rn(r[1].x, r[1].y);
    __half2 x3 = __floats2half2_rn(r[1].z, r[1].w);
    asm volatile("st.shared.v4.b32 [%0], {%1,%2,%3,%4};" :: "r"(a),
                 "r"(*(uint32_t*)&x0), "r"(*(uint32_t*)&x1),
                 "r"(*(uint32_t*)&x2), "r"(*(uint32_t*)&x3) : "memory");
}

__global__ void wconv_kernel(const float* __restrict__ W) {
    int i = (blockIdx.x * blockDim.x + threadIdx.x) * 4;
    float4 v = *(const float4*)(W + i);
    __half2 h0 = __floats2half2_rn(v.x, v.y);
    __half2 h1 = __floats2half2_rn(v.z, v.w);
    *(__half2*)(g_Wh + i)     = h0;
    *(__half2*)(g_Wh + i + 2) = h1;
}

__global__ void __launch_bounds__(THREADS, 1)
fused_gemm_ln_lrelu(const float* __restrict__ x,
                    const float* __restrict__ bias, const float* __restrict__ gamma,
                    const float* __restrict__ beta, float* __restrict__ out) {
    extern __shared__ __align__(1024) char smem[];
    const uint32_t sb = smem_u32(smem);
    const int tid  = threadIdx.x;
    const int lane = tid & 31;
    const int wid  = tid >> 5;          // 0..15
    const int q    = lane & 3;
    const int g    = lane >> 2;
    const int mh   = wid >> 3;          // M half: rows [32*mh, +32)
    const int nw   = wid & 7;           // N slice: cols [64*nw, +64)
    const int m0   = blockIdx.x * TILE_M;

    ((float*)(smem + SM_BIAS))[tid]  = bias[tid];
    ((float*)(smem + SM_GAMMA))[tid] = gamma[tid];
    ((float*)(smem + SM_BETA))[tid]  = beta[tid];

    float acc[2][8][4];
#pragma unroll
    for (int mt = 0; mt < 2; mt++)
#pragma unroll
        for (int nt = 0; nt < 8; nt++)
#pragma unroll
            for (int u = 0; u < 4; u++) acc[mt][nt][u] = 0.f;

    // -------- per-lane ldmatrix address components --------
    const int mr0 = mh * 32 + (lane & 15);        // mt=0 row
    const int mr1 = mr0 + 16;                     // mt=1 row
    const int agsel = lane >> 4;                  // 0/1 (k-low/high granule)
    const uint32_t aoff0 = (uint32_t)(mr0 * 128);
    const uint32_t aoff1 = (uint32_t)(mr1 * 128);
    const int m7_0 = mr0 & 7, m7_1 = mr1 & 7;
    const int wb = nw * 64;
    int n7[4];
    uint32_t boff[4];
    const int bgsel = (lane >> 3) & 1;
#pragma unroll
    for (int p = 0; p < 4; p++) {
        int nr = wb + p * 16 + (lane & 7) + ((lane >> 4) << 3);
        n7[p] = nr & 7;
        boff[p] = (uint32_t)(nr * 128);
    }

    const uint32_t ab = sb + SM_A;
    const uint32_t bb = sb + SM_B;

    // -------- prologue --------
    float4 r[2];
    ldg_A(x, m0, 0, tid, r);
    load_B(0, bb, tid);
    asm volatile("cp.async.commit_group;" ::: "memory");
    sts_A(ab, tid, r);
    ldg_A(x, m0, 1, tid, r);
    load_B(1, bb + B_STAGE, tid);
    asm volatile("cp.async.commit_group;" ::: "memory");

    int bidx = 0;   // B stage of current chunk

#pragma unroll 1
    for (int i = 0; i < N_CHUNKS; i++) {
        if (i < N_CHUNKS - 1) asm volatile("cp.async.wait_group 1;" ::: "memory");
        else                  asm volatile("cp.async.wait_group 0;" ::: "memory");
        __syncthreads();   // B(i),A(i) visible; stages for (i+2)/(i+1) drained

        const uint32_t SA  = ab + (uint32_t)(i & 1) * A_STAGE;
        const uint32_t SBs = bb + (uint32_t)bidx * B_STAGE;

        // prime fragment pipeline (fill latency hides behind cp.async issue below)
        uint32_t af[2][2][4], bf[2][4];
        LDSM4(af[0][0], SA + aoff0 + (uint32_t)((agsel ^ m7_0) << 4));
        LDSM4(af[0][1], SA + aoff1 + (uint32_t)((agsel ^ m7_1) << 4));
        LDSM4(bf[0],    SBs + boff[0] + (uint32_t)((bgsel ^ n7[0]) << 4));

        // issue next loads into drained stages
        if (i + 2 < N_CHUNKS) {
            int b2 = bidx + 2; if (b2 >= 3) b2 -= 3;
            load_B(i + 2, bb + (uint32_t)b2 * B_STAGE, tid);
            asm volatile("cp.async.commit_group;" ::: "memory");
        }
        if (i + 1 < N_CHUNKS) {
            sts_A(ab + (uint32_t)((i + 1) & 1) * A_STAGE, tid, r);
            if (i + 2 < N_CHUNKS) ldg_A(x, m0, i + 2, tid, r);
        }

        // -------- 16-step (ks,p) pipeline: 1 B-LDSM + 4 MMA per step --------
#pragma unroll
        for (int s = 0; s < 16; s++) {
            const int ks = s >> 2, p = s & 3;
            const int cur = s & 1, nxt = cur ^ 1;
            if (s < 15) {
                const int s1 = s + 1, ks1 = s1 >> 2, p1 = s1 & 3;
                LDSM4(bf[nxt], SBs + boff[p1] +
                      (uint32_t)(((2 * ks1 + bgsel) ^ n7[p1]) << 4));
            }
            if (p == 0 && ks < 3) {
                const int c2 = 2 * (ks + 1), nb = (ks + 1) & 1;
                LDSM4(af[nb][0], SA + aoff0 + (uint32_t)(((c2 + agsel) ^ m7_0) << 4));
                LDSM4(af[nb][1], SA + aoff1 + (uint32_t)(((c2 + agsel) ^ m7_1) << 4));
            }
            const int abuf = ks & 1;
            mma_f16(acc[0][2 * p],     af[abuf][0], bf[cur][0], bf[cur][1]);
            mma_f16(acc[0][2 * p + 1], af[abuf][0], bf[cur][2], bf[cur][3]);
            mma_f16(acc[1][2 * p],     af[abuf][1], bf[cur][0], bf[cur][1]);
            mma_f16(acc[1][2 * p + 1], af[abuf][1], bf[cur][2], bf[cur][3]);
        }

        if (++bidx == 3) bidx = 0;
    }

    // ---------------- epilogue ----------------
    const float* bs = (const float*)(smem + SM_BIAS);
    const float* gs = (const float*)(smem + SM_GAMMA);
    const float* es = (const float*)(smem + SM_BETA);
    float* rsum  = (float*)(smem + SM_RSUM);
    float* rsq   = (float*)(smem + SM_RSQ);
    float* smean = (float*)(smem + SM_MEAN);
    float* srstd = (float*)(smem + SM_RSTD);
    const uint32_t mbase = (uint32_t)(mh * 32);

#pragma unroll
    for (int nt = 0; nt < 8; nt++) {
        int c0 = wb + 8 * nt + 2 * q;
        float b0 = bs[c0], b1 = bs[c0 + 1];
#pragma unroll
        for (int mt = 0; mt < 2; mt++) {
            acc[mt][nt][0] += b0; acc[mt][nt][1] += b1;
            acc[mt][nt][2] += b0; acc[mt][nt][3] += b1;
        }
    }

    float sA[2], qA[2], sB[2], qB[2];
#pragma unroll
    for (int mt = 0; mt < 2; mt++) {
        float s0 = 0.f, q0 = 0.f, s1 = 0.f, q1 = 0.f;
#pragma unroll
        for (int nt = 0; nt < 8; nt++) {
            float v0 = acc[mt][nt][0], v1 = acc[mt][nt][1];
            float v2 = acc[mt][nt][2], v3 = acc[mt][nt][3];
            s0 += v0 + v1;  q0 += v0 * v0 + v1 * v1;
            s1 += v2 + v3;  q1 += v2 * v2 + v3 * v3;
        }
        sA[mt] = s0; qA[mt] = q0; sB[mt] = s1; qB[mt] = q1;
    }
#pragma unroll
    for (int off = 1; off <= 2; off <<= 1) {
#pragma unroll
        for (int mt = 0; mt < 2; mt++) {
            sA[mt] += __shfl_xor_sync(0xffffffffu, sA[mt], off);
            qA[mt] += __shfl_xor_sync(0xffffffffu, qA[mt], off);
            sB[mt] += __shfl_xor_sync(0xffffffffu, sB[mt], off);
            qB[mt] += __shfl_xor_sync(0xffffffffu, qB[mt], off);
        }
    }
    if (q == 0) {
#pragma unroll
        for (int mt = 0; mt < 2; mt++) {
            int rA = (int)mbase + 16 * mt + g;
            rsum[rA * 8 + nw]       = sA[mt];
            rsq [rA * 8 + nw]       = qA[mt];
            rsum[(rA + 8) * 8 + nw] = sB[mt];
            rsq [(rA + 8) * 8 + nw] = qB[mt];
        }
    }
    __syncthreads();

    if (tid < 64) {
        float s = 0.f, ss = 0.f;
#pragma unroll
        for (int w = 0; w < 8; w++) { s += rsum[tid * 8 + w]; ss += rsq[tid * 8 + w]; }
        float mean = s * (1.0f / 512.0f);
        float var  = ss * (1.0f / 512.0f) - mean * mean;
        smean[tid] = mean;
        srstd[tid] = rsqrtf(var + 1e-5f);
    }
    __syncthreads();

    const uint32_t OS = sb + SM_B;   // staging reuses B region (guarded by syncs above)
#pragma unroll
    for (int mt = 0; mt < 2; mt++) {
        int rA = (int)mbase + 16 * mt + g, rB = rA + 8;
        float mA = smean[rA], rsdA = srstd[rA];
        float mB = smean[rB], rsdB = srstd[rB];
#pragma unroll
        for (int nt = 0; nt < 8; nt++) {
            int c0 = wb + 8 * nt + 2 * q;
            float g0 = gs[c0], g1 = gs[c0 + 1];
            float e0 = es[c0], e1 = es[c0 + 1];
            float t0 = (acc[mt][nt][0] - mA) * rsdA * g0 + e0;
            float t1 = (acc[mt][nt][1] - mA) * rsdA * g1 + e1;
            float t2 = (acc[mt][nt][2] - mB) * rsdB * g0 + e0;
            float t3 = (acc[mt][nt][3] - mB) * rsdB * g1 + e1;
            t0 = fmaxf(t0, 0.2f * t0);
            t1 = fmaxf(t1, 0.2f * t1);
            t2 = fmaxf(t2, 0.2f * t2);
            t3 = fmaxf(t3, 0.2f * t3);
            uint32_t a0 = OS + (uint32_t)(rA * OUT_STRIDE_W + c0) * 4;
            uint32_t a1 = OS + (uint32_t)(rB * OUT_STRIDE_W + c0) * 4;
            asm volatile("st.shared.v2.f32 [%0], {%1, %2};" :: "r"(a0), "f"(t0), "f"(t1) : "memory");
            asm volatile("st.shared.v2.f32 [%0], {%1, %2};" :: "r"(a1), "f"(t2), "f"(t3) : "memory");
        }
    }
    __syncthreads();

    // coalesced writeback: 64 rows x 512 f32 = 8192 float4s
#pragma unroll
    for (int it = 0; it < 16; it++) {
        int id  = it * THREADS + tid;
        int row = id >> 7;
        int j   = id & 127;
        int gr  = m0 + row;
        if (gr < N_NODES) {
            uint32_t a = OS + (uint32_t)(row * OUT_STRIDE_W + j * 4) * 4;
            uint32_t v0, v1, v2, v3;
            asm volatile("ld.shared.v4.b32 {%0, %1, %2, %3}, [%4];"
                         : "=r"(v0), "=r"(v1), "=r"(v2), "=r"(v3) : "r"(a));
            float4 o;
            o.x = __uint_as_float(v0); o.y = __uint_as_float(v1);
            o.z = __uint_as_float(v2); o.w = __uint_as_float(v3);
            *(float4*)(out + (size_t)gr * DIM + j * 4) = o;
        }
    }
}

extern "C" void kernel_launch(void* const* d_in, const int* in_sizes, int n_in,
                              void* d_out, int out_size) {
    const float* x     = (const float*)d_in[0];
    // d_in[1] edge_attr, d_in[2] edge_index, d_in[3] batch: dead inputs
    const float* W     = (const float*)d_in[4];
    const float* bias  = (const float*)d_in[5];
    const float* gamma = (const float*)d_in[6];
    const float* beta  = (const float*)d_in[7];
    float* out = (float*)d_out;

    wconv_kernel<<<256, 256>>>(W);

    cudaFuncSetAttribute(fused_gemm_ln_lrelu,
                         cudaFuncAttributeMaxDynamicSharedMemorySize, SMEM_TOTAL);
    fused_gemm_ln_lrelu<<<NUM_TILES, THREADS, SMEM_TOTAL>>>(x, bias, gamma, beta, out);
}